// round 5
// baseline (speedup 1.0000x reference)
#include <cuda_runtime.h>
#include <cstdint>

// Board: 64x64, 8 channels, channels-last float32. HW = 4096 cells.
// One CTA per board, 256 threads. Each thread owns 4 consecutive cells in
// each of 4 groups: cell = g*1024 + 4*tid + j. 16 front-batched LDG.128,
// 4 STG.128 writeback.

#define HW_       4096
#define NTHREADS  256
#define NW        8
#define IMAXS     0x7fffffff

__device__ __forceinline__ void merge2min_i(int& m1, int& i1, int& m2,
                                            int m1b, int i1b, int m2b) {
    // (smallest d^2, row-major argmin, second-smallest d^2)
    if (m1b < m1 || (m1b == m1 && i1b < i1)) {
        m2 = min(m1, m2b);
        m1 = m1b; i1 = i1b;
    } else {
        m2 = min(m2, m1b);
    }
}

__global__ __launch_bounds__(NTHREADS, 4)
void oracle_kernel(const float* __restrict__ x,
                   const float* __restrict__ opp_start,
                   float* __restrict__ out) {
    const int b   = blockIdx.x;
    const int tid = threadIdx.x;
    const int wid = tid >> 5;
    const int lid = tid & 31;

    // Each cell = 32 bytes; first float4 holds channels 0..3:
    // .y = channel 1 (food), .w = channel 3 (opp).
    const float4* xb = reinterpret_cast<const float4*>(x) + (size_t)b * HW_ * 2;

    // ---------------- Phase 1: 16 front-batched LDG.128 ----------------------
    float4 v[16];
#pragma unroll
    for (int g = 0; g < 4; g++)
#pragma unroll
        for (int j = 0; j < 4; j++) {
            const int cell = (g << 10) + (tid << 2) + j;
            v[(g << 2) + j] = xb[2 * cell];
        }

    unsigned foodmask = 0;
    int nf = 0, no = 0;
    int fo = IMAXS;   // first-opp candidate (min row-major idx)
#pragma unroll
    for (int g = 0; g < 4; g++)
#pragma unroll
        for (int j = 0; j < 4; j++) {
            const int k = (g << 2) + j;
            const int cell = (g << 10) + (tid << 2) + j;
            const bool food = (v[k].y == 1.0f);
            const bool opp  = (v[k].w == 1.0f);
            foodmask |= (unsigned)food << k;
            nf += food;
            no += opp;
            if (opp && cell < fo) fo = cell;
        }

    nf = __reduce_add_sync(0xffffffffu, nf);
    no = __reduce_add_sync(0xffffffffu, no);
    fo = __reduce_min_sync(0xffffffffu, fo);

    __shared__ int s_nf[NW], s_no[NW], s_fo[NW], s_i1[NW], s_m1[NW], s_m2[NW];

    if (lid == 0) { s_nf[wid] = nf; s_no[wid] = no; s_fo[wid] = fo; }
    __syncthreads();

    int tot_nf = 0, tot_no = 0, tfo = IMAXS;
#pragma unroll
    for (int w = 0; w < NW; w++) {
        tot_nf += s_nf[w];
        tot_no += s_no[w];
        tfo = min(tfo, s_fo[w]);
    }
    if (tfo == IMAXS) tfo = 0;       // argmax over all-False == 0 (JAX semantics)
    const int orow = tfo >> 6;
    const int ocol = tfo & 63;

    // ---------------- Phase 2: two-smallest food d^2 (integer, exact) --------
    int m1 = IMAXS, m2 = IMAXS;
    int i1 = 0;                       // argmin over all-INF row == 0
#pragma unroll
    for (int g = 0; g < 4; g++)
#pragma unroll
        for (int j = 0; j < 4; j++) {
            const int k = (g << 2) + j;
            if ((foodmask >> k) & 1u) {
                const int cell = (g << 10) + (tid << 2) + j;
                const int dr = (cell >> 6) - orow;
                const int dc = (cell & 63) - ocol;
                const int d2 = dr * dr + dc * dc;
                if (d2 < m1) { m2 = m1; m1 = d2; i1 = cell; }
                else         { m2 = min(m2, d2); }
            }
        }

#pragma unroll
    for (int off = 16; off; off >>= 1) {
        const int m1b = __shfl_xor_sync(0xffffffffu, m1, off);
        const int i1b = __shfl_xor_sync(0xffffffffu, i1, off);
        const int m2b = __shfl_xor_sync(0xffffffffu, m2, off);
        merge2min_i(m1, i1, m2, m1b, i1b, m2b);
    }
    if (lid == 0) { s_m1[wid] = m1; s_i1[wid] = i1; s_m2[wid] = m2; }
    __syncthreads();

    int M1 = s_m1[0], M2 = s_m2[0], I1 = s_i1[0];
#pragma unroll
    for (int w = 1; w < NW; w++) {
        merge2min_i(M1, I1, M2, s_m1[w], s_i1[w], s_m2[w]);
    }

    // ---------------- Branch logic (redundant per thread) --------------------
    const float os0 = __ldg(&opp_start[0]);
    const float os1 = __ldg(&opp_start[1]);
    const bool matches_start = ((float)orow == os0) && ((float)ocol == os1);
    const bool branchA = (tot_nf > 1) && (tot_no > 0) && !matches_start;
    // diff only consumed when tot_nf > 1 (M1, M2 finite there); f32 sqrt of
    // exact ints matches the reference bit-for-bit.
    const float diff = __fsqrt_rn((float)(M2 == IMAXS ? 0 : M2))
                     - __fsqrt_rn((float)(M1 == IMAXS ? 0 : M1));
    const bool ambiguous    = (branchA && (diff <  0.1f)) || ((tot_nf > 1) && !branchA);
    const bool pick_nearest = (branchA && (diff >= 0.1f)) || (tot_nf == 1);

    // ---------------- Writeback: 4 x STG.128 ---------------------------------
    float4* ob4 = reinterpret_cast<float4*>(out + (size_t)b * HW_);
#pragma unroll
    for (int g = 0; g < 4; g++) {
        float4 o;
        float* op = &o.x;
#pragma unroll
        for (int j = 0; j < 4; j++) {
            const int k = (g << 2) + j;
            const int cell = (g << 10) + (tid << 2) + j;
            const bool fbit = (foodmask >> k) & 1u;
            const bool hit = ambiguous ? fbit : (pick_nearest && (cell == I1));
            op[j] = hit ? 10.0f : -10.0f;
        }
        ob4[(g << 8) + tid] = o;
    }
}

extern "C" void kernel_launch(void* const* d_in, const int* in_sizes, int n_in,
                              void* d_out, int out_size) {
    const float* x         = (const float*)d_in[0];
    const float* opp_start = (const float*)d_in[1];
    float* out = (float*)d_out;

    const int B = in_sizes[0] / (HW_ * 8);   // 4096
    oracle_kernel<<<B, NTHREADS>>>(x, opp_start, out);
}

// round 6
// speedup vs baseline: 1.3848x; 1.3848x over previous
#include <cuda_runtime.h>
#include <cstdint>

// Board: 64x64, 8 channels, channels-last float32. HW = 4096 cells.
// One CTA per board, 256 threads x 16 cells (lane-contiguous: cell = k*256+tid,
// minimal 8 lines per warp LDG.128). Shared food bitmap decouples the store
// mapping so writeback is 4 x STG.128 per thread.

#define HW_       4096
#define NTHREADS  256
#define CELLS     16
#define NW        8
#define IMAXS     0x7fffffff

__device__ __forceinline__ void merge2min_i(int& m1, int& i1, int& m2,
                                            int m1b, int i1b, int m2b) {
    // (smallest d^2, row-major argmin, second-smallest d^2)
    if (m1b < m1 || (m1b == m1 && i1b < i1)) {
        m2 = min(m1, m2b);
        m1 = m1b; i1 = i1b;
    } else {
        m2 = min(m2, m1b);
    }
}

__global__ __launch_bounds__(NTHREADS, 4)
void oracle_kernel(const float* __restrict__ x,
                   const float* __restrict__ opp_start,
                   float* __restrict__ out) {
    const int b   = blockIdx.x;
    const int tid = threadIdx.x;
    const int wid = tid >> 5;
    const int lid = tid & 31;

    __shared__ unsigned s_bitmap[HW_ / 32];                 // food bit per cell
    __shared__ int s_nf[NW], s_no[NW], s_fo[NW], s_i1[NW], s_m1[NW], s_m2[NW];

    // Each cell = 32 bytes; first float4 holds channels 0..3:
    // .y = channel 1 (food), .w = channel 3 (opp).
    const float4* xb = reinterpret_cast<const float4*>(x) + (size_t)b * HW_ * 2;

    // ---------------- Phase 1: 16 front-batched LDG.128 (lane-contiguous) ----
    float4 v[CELLS];
#pragma unroll
    for (int k = 0; k < CELLS; k++) {
        v[k] = xb[2 * (k * NTHREADS + tid)];
    }

    unsigned foodmask = 0;
    int nf = 0, no = 0;
    int fo = IMAXS;   // first-opp candidate (min row-major idx)
#pragma unroll
    for (int k = 0; k < CELLS; k++) {
        const int cell = k * NTHREADS + tid;
        const bool food = (v[k].y == 1.0f);
        const bool opp  = (v[k].w == 1.0f);
        // cells [k*256 + 32*wid, +32) form one contiguous bitmap word
        const unsigned bal = __ballot_sync(0xffffffffu, food);
        if (lid == 0) s_bitmap[(k << 3) + wid] = bal;
        foodmask |= (unsigned)food << k;
        nf += food;
        no += opp;
        if (opp && cell < fo) fo = cell;
    }

    nf = __reduce_add_sync(0xffffffffu, nf);
    no = __reduce_add_sync(0xffffffffu, no);
    fo = __reduce_min_sync(0xffffffffu, fo);
    if (lid == 0) { s_nf[wid] = nf; s_no[wid] = no; s_fo[wid] = fo; }
    __syncthreads();   // fences s_bitmap too

    int tot_nf = 0, tot_no = 0, tfo = IMAXS;
#pragma unroll
    for (int w = 0; w < NW; w++) {
        tot_nf += s_nf[w];
        tot_no += s_no[w];
        tfo = min(tfo, s_fo[w]);
    }
    if (tfo == IMAXS) tfo = 0;       // argmax over all-False == 0 (JAX semantics)
    const int orow = tfo >> 6;
    const int ocol = tfo & 63;

    // ---------------- Phase 2: two-smallest food d^2 (integer, exact) --------
    int m1 = IMAXS, m2 = IMAXS;
    int i1 = 0;                       // argmin over all-INF row == 0
#pragma unroll
    for (int k = 0; k < CELLS; k++) {
        const int cell = k * NTHREADS + tid;
        if ((foodmask >> k) & 1u) {
            const int dr = (cell >> 6) - orow;
            const int dc = (cell & 63) - ocol;
            const int d2 = dr * dr + dc * dc;
            if (d2 < m1) { m2 = m1; m1 = d2; i1 = cell; }
            else         { m2 = min(m2, d2); }
        }
    }

#pragma unroll
    for (int off = 16; off; off >>= 1) {
        const int m1b = __shfl_xor_sync(0xffffffffu, m1, off);
        const int i1b = __shfl_xor_sync(0xffffffffu, i1, off);
        const int m2b = __shfl_xor_sync(0xffffffffu, m2, off);
        merge2min_i(m1, i1, m2, m1b, i1b, m2b);
    }
    if (lid == 0) { s_m1[wid] = m1; s_i1[wid] = i1; s_m2[wid] = m2; }
    __syncthreads();

    int M1 = s_m1[0], M2 = s_m2[0], I1 = s_i1[0];
#pragma unroll
    for (int w = 1; w < NW; w++) {
        merge2min_i(M1, I1, M2, s_m1[w], s_i1[w], s_m2[w]);
    }

    // ---------------- Branch logic (redundant per thread) --------------------
    const float os0 = __ldg(&opp_start[0]);
    const float os1 = __ldg(&opp_start[1]);
    const bool matches_start = ((float)orow == os0) && ((float)ocol == os1);
    const bool branchA = (tot_nf > 1) && (tot_no > 0) && !matches_start;
    // diff only consumed when tot_nf > 1 (M1, M2 finite there); f32 sqrt of
    // exact ints matches the reference bit-for-bit.
    const float diff = __fsqrt_rn((float)(M2 == IMAXS ? 0 : M2))
                     - __fsqrt_rn((float)(M1 == IMAXS ? 0 : M1));
    const bool ambiguous    = (branchA && (diff <  0.1f)) || ((tot_nf > 1) && !branchA);
    const bool pick_nearest = (branchA && (diff >= 0.1f)) || (tot_nf == 1);

    // ---------------- Writeback: 4 x STG.128 via shared bitmap ---------------
    float4* ob4 = reinterpret_cast<float4*>(out + (size_t)b * HW_);
#pragma unroll
    for (int g = 0; g < 4; g++) {
        const int c0 = (g << 10) + (tid << 2);              // 4 consecutive cells
        const unsigned wbits = s_bitmap[c0 >> 5] >> (c0 & 31);
        float4 o;
        float* op = &o.x;
#pragma unroll
        for (int j = 0; j < 4; j++) {
            const bool fbit = (wbits >> j) & 1u;
            const bool hit = ambiguous ? fbit : (pick_nearest && (c0 + j == I1));
            op[j] = hit ? 10.0f : -10.0f;
        }
        ob4[(g << 8) + tid] = o;
    }
}

extern "C" void kernel_launch(void* const* d_in, const int* in_sizes, int n_in,
                              void* d_out, int out_size) {
    const float* x         = (const float*)d_in[0];
    const float* opp_start = (const float*)d_in[1];
    float* out = (float*)d_out;

    const int B = in_sizes[0] / (HW_ * 8);   // 4096
    oracle_kernel<<<B, NTHREADS>>>(x, opp_start, out);
}